// round 16
// baseline (speedup 1.0000x reference)
#include <cuda_runtime.h>
#include <cuda_bf16.h>
#include <cstdint>

// ---------------------------------------------------------------------------
// Aligner, algebraic form:
//   softmax(ex@eo^T) == softmax(ix@(W^T W)@io^T + 1 v^T),  v = io @ (W^T b)
//   out = softmax(...) @ io
// Chain: M = W^T W (split-K z=8) ; T = ix M ; S = T io^T ;
//        P = softmax(S+v) ; out = P io (NN via ldmatrix.trans)
// R15: R14 heterogeneous fusion with the reduce8 grid fixed (1024 CTAs, the
//      4096-CTA launch read past g_mp and crashed).
// ---------------------------------------------------------------------------

typedef unsigned short u16;  // raw bf16 bits

// ======================= scratch (device globals) ===========================
__device__ u16   g_wts [1024L * 2048];      // W^T split
__device__ float g_mp  [8L * 1024 * 1024];  // M split-K partials (fp32, z=8)
__device__ u16   g_ms  [1024L * 2048];      // M = W^T W split
__device__ u16   g_ixs [16384L * 2048];     // ix split
__device__ u16   g_ios [16384L * 2048];     // io split
__device__ u16   g_ts  [16384L * 2048];     // T = ix M split
__device__ float g_sc  [32L * 512 * 512];   // scores fp32
__device__ u16   g_ps  [32L * 512 * 1024];  // softmax probs split
__device__ float g_wtb [1024];              // W^T b  (atomic accum)
__device__ float g_v   [16384];             // io @ (W^T b)  (atomic accum)

// ======================= PTX helpers ========================================
__device__ __forceinline__ uint32_t smem_u32(const void* p) {
    uint32_t a;
    asm("{ .reg .u64 t; cvta.to.shared.u64 t, %1; cvt.u32.u64 %0, t; }"
        : "=r"(a) : "l"(p));
    return a;
}

__device__ __forceinline__ void cp_async16(uint32_t saddr, const void* gaddr) {
    asm volatile("cp.async.cg.shared.global [%0], [%1], 16;"
                 :: "r"(saddr), "l"(gaddr) : "memory");
}
__device__ __forceinline__ void cp_commit() {
    asm volatile("cp.async.commit_group;" ::: "memory");
}
template <int N>
__device__ __forceinline__ void cp_wait() {
    asm volatile("cp.async.wait_group %0;" :: "n"(N) : "memory");
}

__device__ __forceinline__ void ldsm_x4(uint32_t* r, uint32_t addr) {
    asm volatile("ldmatrix.sync.aligned.m8n8.x4.shared.b16 {%0,%1,%2,%3}, [%4];"
                 : "=r"(r[0]), "=r"(r[1]), "=r"(r[2]), "=r"(r[3]) : "r"(addr));
}
__device__ __forceinline__ void ldsm_x4_trans(uint32_t* r, uint32_t addr) {
    asm volatile("ldmatrix.sync.aligned.m8n8.x4.trans.shared.b16 {%0,%1,%2,%3}, [%4];"
                 : "=r"(r[0]), "=r"(r[1]), "=r"(r[2]), "=r"(r[3]) : "r"(addr));
}

__device__ __forceinline__ void mma_bf16(float* c, const uint32_t* a,
                                         const uint32_t* b) {
    asm volatile(
        "mma.sync.aligned.m16n8k16.row.col.f32.bf16.bf16.f32 "
        "{%0,%1,%2,%3}, {%4,%5,%6,%7}, {%8,%9}, {%0,%1,%2,%3};"
        : "+f"(c[0]), "+f"(c[1]), "+f"(c[2]), "+f"(c[3])
        : "r"(a[0]), "r"(a[1]), "r"(a[2]), "r"(a[3]), "r"(b[0]), "r"(b[1]));
}

// ======================= split helpers ======================================
__device__ __forceinline__ void split2(float v, __nv_bfloat16& h, __nv_bfloat16& l) {
    h = __float2bfloat16(v);
    l = __float2bfloat16(v - __bfloat162float(h));
}

__device__ __forceinline__ void store_split4(u16* oh, u16* ol, float4 a) {
    __nv_bfloat16 h0, h1, h2, h3, l0, l1, l2, l3;
    split2(a.x, h0, l0); split2(a.y, h1, l1); split2(a.z, h2, l2); split2(a.w, h3, l3);
    *reinterpret_cast<__nv_bfloat162*>(oh)     = __halves2bfloat162(h0, h1);
    *reinterpret_cast<__nv_bfloat162*>(oh + 2) = __halves2bfloat162(h2, h3);
    *reinterpret_cast<__nv_bfloat162*>(ol)     = __halves2bfloat162(l0, l1);
    *reinterpret_cast<__nv_bfloat162*>(ol + 2) = __halves2bfloat162(l2, l3);
}

// 128-thread split body: CTA `cta` handles 8 half-rows (512 floats each) of a
// [R,1024] fp32 tensor -> [R, 2048] hi|lo split.
__device__ __forceinline__ void split_body128(int cta, const float* __restrict__ in,
                                              u16* __restrict__ out)
{
    const int t = threadIdx.x;
#pragma unroll
    for (int it = 0; it < 8; it++) {
        const int seg = cta * 8 + it;
        const long r  = seg >> 1;
        const int  cb = (seg & 1) * 512 + t * 4;
        const float4 a = *reinterpret_cast<const float4*>(in + r * 1024 + cb);
        store_split4(out + r * 2048 + cb, out + r * 2048 + 1024 + cb, a);
    }
}

// same + v[r] += sum(row * wtb) partials (warp covers 128 contiguous cols)
__device__ __forceinline__ void split_v_body128(int cta, const float* __restrict__ in,
                                                const float* __restrict__ wtb,
                                                u16* __restrict__ out,
                                                float* __restrict__ v)
{
    const int t = threadIdx.x;
#pragma unroll
    for (int it = 0; it < 8; it++) {
        const int seg = cta * 8 + it;
        const long r  = seg >> 1;
        const int  cb = (seg & 1) * 512 + t * 4;
        const float4 a = *reinterpret_cast<const float4*>(in + r * 1024 + cb);
        const float4 w = *reinterpret_cast<const float4*>(wtb + cb);
        store_split4(out + r * 2048 + cb, out + r * 2048 + 1024 + cb, a);
        float s = a.x * w.x + a.y * w.y + a.z * w.z + a.w * w.w;
#pragma unroll
        for (int o = 16; o > 0; o >>= 1)
            s += __shfl_xor_sync(0xFFFFFFFFu, s, o);
        if ((t & 31) == 0) atomicAdd(&v[r], s);
    }
}

// W^T split + wtb partials in one pass over W.  grid (32, 32), 256 thr.
__global__ void __launch_bounds__(256)
wsplit_wtb_kernel(const float* __restrict__ W, const float* __restrict__ b,
                  u16* __restrict__ out, float* __restrict__ wtb)
{
    __shared__ float t[32][33];
    __shared__ float red[8][32];
    const int d0 = blockIdx.x * 32;
    const int m0 = blockIdx.y * 32;   // e range
    const int tx = threadIdx.x & 31;
    const int ty = threadIdx.x >> 5;
    float part = 0.0f;
#pragma unroll
    for (int i = 0; i < 4; i++) {
        const int e = m0 + ty + 8 * i;
        const float val = W[(long)e * 1024 + d0 + tx];
        t[ty + 8 * i][tx] = val;
        part += val * b[e];
    }
    red[ty][tx] = part;
    __syncthreads();
    if (ty == 0) {
        float s = red[0][tx];
#pragma unroll
        for (int i = 1; i < 8; i++) s += red[i][tx];
        atomicAdd(&wtb[d0 + tx], s);
    }
#pragma unroll
    for (int i = 0; i < 4; i++) {
        const int d = d0 + ty + 8 * i;
        const int m = m0 + tx;
        __nv_bfloat16 h, l;
        split2(t[tx][ty + 8 * i], h, l);
        *reinterpret_cast<__nv_bfloat16*>(&out[(long)d * 2048 + m])        = h;
        *reinterpret_cast<__nv_bfloat16*>(&out[(long)d * 2048 + 1024 + m]) = l;
    }
}

// sum 8 split-K partials of M and split to bf16 hi/lo.  grid MUST be
// (D*D)/1024 = 1024 CTAs (256 thr x 4 floats each).
__global__ void __launch_bounds__(256)
reduce8_split_kernel(const float* __restrict__ p, u16* __restrict__ out)
{
    const long e = ((long)blockIdx.x * 256 + threadIdx.x) * 4;
    const long r = e >> 10;
    const int  c = (int)(e & 1023);
    float4 a = *reinterpret_cast<const float4*>(p + e);
#pragma unroll
    for (int s = 1; s < 8; s++) {
        const float4 b = *reinterpret_cast<const float4*>(p + (long)s * 1048576 + e);
        a.x += b.x; a.y += b.y; a.z += b.z; a.w += b.w;
    }
    store_split4(out + r * 2048 + c, out + r * 2048 + 1024 + c, a);
}

// ======================= mma.sync GEMM engine (device body) =================
// NT (BTRANS=0): C = A[M,2Kfull] (*) B[N,2Kfull], B row-major [N,K].
// NN (BTRANS=1): C = A[M,2Kfull] (*) B[K,ldb] row-major; hi at col0, lo at
//                col0+loOff; fragments via ldmatrix.trans.
// 3 bf16 phases, fp32 accumulate. CTA 128x128, 4 warps (2Mx2N of 64x64),
// 2-stage cp.async, 2 CTAs/SM.
#define LDS_STRIDE 40
#define BSTRIDE 136
#define TILE_BYTES (128 * LDS_STRIDE * 2)
#define STAGE_BYTES (4 * TILE_BYTES)
#define GEMM_SMEM (2 * STAGE_BYTES)

template <int MODE, int BTRANS>
__device__ __forceinline__ void
gemm_body(int gbx, int gby, int gbz,
          const u16* __restrict__ A, const u16* __restrict__ B,
          const float* __restrict__ bias, float* __restrict__ Cf,
          u16* __restrict__ Cs,
          int K, int Kfull, int kPerZ,
          long sA, long sB, long sC, int ldc, int loOff, int ldb)
{
    extern __shared__ char dynsmem[];

    const int tid  = threadIdx.x;
    const int wid  = tid >> 5;
    const int lane = tid & 31;

    const long bz = gbz;
    A += bz * sA;
    B += bz * sB;
    const int kbase = (int)bz * kPerZ;
    const int row0 = gby * 128;
    const int col0 = gbx * 128;
    const long lda = 2L * Kfull;

    const int nkc = K / 32;

    const uint32_t sbase = smem_u32(dynsmem);

    const int cr0 = tid >> 2;
    const int cc  = tid & 3;

    const int warp_m = wid & 1;
    const int warp_n = wid >> 1;

    float acc[4][8][4];
#pragma unroll
    for (int mt = 0; mt < 4; mt++)
#pragma unroll
        for (int nt = 0; nt < 8; nt++)
#pragma unroll
            for (int i = 0; i < 4; i++) acc[mt][nt][i] = 0.0f;

    const int a_row = warp_m * 64 + (lane & 15);
    const int a_colb = (lane >> 4) << 3;
    const int b_row = warp_n * 64 + (lane & 7) + ((lane >> 4) << 3);
    const int b_colb = ((lane >> 3) & 1) << 3;
    const int bk = (lane & 7) + (((lane >> 3) & 1) << 3);
    const int bn = warp_n * 64 + ((lane >> 4) << 3);

    auto stage_copy = [&](int s, int kc) {
        const uint32_t sb0 = sbase + (uint32_t)s * STAGE_BYTES;
        const int hoff = kbase + kc * 32;
        const int loff = Kfull + kbase + kc * 32;
#pragma unroll
        for (int j = 0; j < 4; j++) {
            const int r = cr0 + 32 * j;
            const uint32_t so = (uint32_t)r * (LDS_STRIDE * 2) + (uint32_t)cc * 16u;
            const u16* arow = A + (long)(row0 + r) * lda + cc * 8;
            cp_async16(sb0 + 0 * TILE_BYTES + so, arow + hoff);
            cp_async16(sb0 + 1 * TILE_BYTES + so, arow + loff);
        }
        if (!BTRANS) {
#pragma unroll
            for (int j = 0; j < 4; j++) {
                const int r = cr0 + 32 * j;
                const uint32_t so = (uint32_t)r * (LDS_STRIDE * 2) + (uint32_t)cc * 16u;
                const u16* brow = B + (long)(col0 + r) * lda + cc * 8;
                cp_async16(sb0 + 2 * TILE_BYTES + so, brow + hoff);
                cp_async16(sb0 + 3 * TILE_BYTES + so, brow + loff);
            }
        } else {
#pragma unroll
            for (int j = 0; j < 4; j++) {
                const int vv = tid + 128 * j;
                const int krow = vv >> 4;
                const int vc   = vv & 15;
                const uint32_t so = (uint32_t)krow * (BSTRIDE * 2) + (uint32_t)vc * 16u;
                const u16* brow = B + (long)(kbase + kc * 32 + krow) * ldb
                                    + col0 + vc * 8;
                cp_async16(sb0 + 2 * TILE_BYTES + so, brow);
                cp_async16(sb0 + 3 * TILE_BYTES + so, brow + loOff);
            }
        }
        cp_commit();
    };

    stage_copy(0, 0);

    for (int kc = 0; kc < nkc; kc++) {
        cp_wait<0>();
        __syncthreads();

        const uint32_t st = sbase + (uint32_t)(kc & 1) * STAGE_BYTES;
        const uint32_t stAl = st + 1 * TILE_BYTES;
        const uint32_t stBh = st + 2 * TILE_BYTES;
        const uint32_t stBl = st + 3 * TILE_BYTES;

        uint32_t ah[4][4], al[4][4], bh[8][2], bl[8][2];
        {
            const uint32_t a_off =
                (uint32_t)a_row * (LDS_STRIDE * 2) + (uint32_t)a_colb * 2;
#pragma unroll
            for (int mt = 0; mt < 4; mt++) {
                const uint32_t ao = a_off + (uint32_t)(mt * 16) * (LDS_STRIDE * 2);
                ldsm_x4(ah[mt], st + ao);
                ldsm_x4(al[mt], stAl + ao);
            }
#pragma unroll
            for (int nt2 = 0; nt2 < 4; nt2++) {
                uint32_t r4[4], s4[4];
                if (!BTRANS) {
                    const uint32_t bo =
                        (uint32_t)(b_row + nt2 * 16) * (LDS_STRIDE * 2) +
                        (uint32_t)b_colb * 2;
                    ldsm_x4(r4, stBh + bo);
                    ldsm_x4(s4, stBl + bo);
                } else {
                    const uint32_t bo =
                        (uint32_t)bk * (BSTRIDE * 2) +
                        (uint32_t)(bn + nt2 * 16) * 2;
                    ldsm_x4_trans(r4, stBh + bo);
                    ldsm_x4_trans(s4, stBl + bo);
                }
                bh[2 * nt2][0] = r4[0]; bh[2 * nt2][1] = r4[1];
                bh[2 * nt2 + 1][0] = r4[2]; bh[2 * nt2 + 1][1] = r4[3];
                bl[2 * nt2][0] = s4[0]; bl[2 * nt2][1] = s4[1];
                bl[2 * nt2 + 1][0] = s4[2]; bl[2 * nt2 + 1][1] = s4[3];
            }
        }

        if (kc + 1 < nkc) stage_copy((kc + 1) & 1, kc + 1);

#pragma unroll
        for (int mt = 0; mt < 4; mt++)
#pragma unroll
            for (int nt = 0; nt < 8; nt++)
                mma_bf16(acc[mt][nt], ah[mt], bh[nt]);
#pragma unroll
        for (int mt = 0; mt < 4; mt++)
#pragma unroll
            for (int nt = 0; nt < 8; nt++)
                mma_bf16(acc[mt][nt], ah[mt], bl[nt]);
#pragma unroll
        for (int mt = 0; mt < 4; mt++)
#pragma unroll
            for (int nt = 0; nt < 8; nt++)
                mma_bf16(acc[mt][nt], al[mt], bh[nt]);

        {
            const uint32_t a_off =
                (uint32_t)a_row * (LDS_STRIDE * 2) + (uint32_t)(16 + a_colb) * 2;
#pragma unroll
            for (int mt = 0; mt < 4; mt++) {
                const uint32_t ao = a_off + (uint32_t)(mt * 16) * (LDS_STRIDE * 2);
                ldsm_x4(ah[mt], st + ao);
                ldsm_x4(al[mt], stAl + ao);
            }
#pragma unroll
            for (int nt2 = 0; nt2 < 4; nt2++) {
                uint32_t r4[4], s4[4];
                if (!BTRANS) {
                    const uint32_t bo =
                        (uint32_t)(b_row + nt2 * 16) * (LDS_STRIDE * 2) +
                        (uint32_t)(16 + b_colb) * 2;
                    ldsm_x4(r4, stBh + bo);
                    ldsm_x4(s4, stBl + bo);
                } else {
                    const uint32_t bo =
                        (uint32_t)(16 + bk) * (BSTRIDE * 2) +
                        (uint32_t)(bn + nt2 * 16) * 2;
                    ldsm_x4_trans(r4, stBh + bo);
                    ldsm_x4_trans(s4, stBl + bo);
                }
                bh[2 * nt2][0] = r4[0]; bh[2 * nt2][1] = r4[1];
                bh[2 * nt2 + 1][0] = r4[2]; bh[2 * nt2 + 1][1] = r4[3];
                bl[2 * nt2][0] = s4[0]; bl[2 * nt2][1] = s4[1];
                bl[2 * nt2 + 1][0] = s4[2]; bl[2 * nt2 + 1][1] = s4[3];
            }
        }
#pragma unroll
        for (int mt = 0; mt < 4; mt++)
#pragma unroll
            for (int nt = 0; nt < 8; nt++)
                mma_bf16(acc[mt][nt], ah[mt], bh[nt]);
#pragma unroll
        for (int mt = 0; mt < 4; mt++)
#pragma unroll
            for (int nt = 0; nt < 8; nt++)
                mma_bf16(acc[mt][nt], ah[mt], bl[nt]);
#pragma unroll
        for (int mt = 0; mt < 4; mt++)
#pragma unroll
            for (int nt = 0; nt < 8; nt++)
                mma_bf16(acc[mt][nt], al[mt], bh[nt]);
    }

    // ---- epilogue ----
    const int er0 = row0 + warp_m * 64 + (lane >> 2);
    const int ec0 = col0 + warp_n * 64 + (lane & 3) * 2;
#pragma unroll
    for (int mt = 0; mt < 4; mt++) {
#pragma unroll
        for (int nt = 0; nt < 8; nt++) {
            const int r0 = er0 + mt * 16;
            const int r1 = r0 + 8;
            const int c  = ec0 + nt * 8;
            if (MODE == 0) {
                float2 v0, v1;
                v0.x = acc[mt][nt][0]; v0.y = acc[mt][nt][1];
                v1.x = acc[mt][nt][2]; v1.y = acc[mt][nt][3];
                *reinterpret_cast<float2*>(Cf + bz * sC + (long)r0 * ldc + c) = v0;
                *reinterpret_cast<float2*>(Cf + bz * sC + (long)r1 * ldc + c) = v1;
            } else {
                const float b0 = bias ? bias[c] : 0.0f;
                const float b1 = bias ? bias[c + 1] : 0.0f;
                __nv_bfloat16 h0, h1, l0, l1;
                u16* q0 = Cs + (long)r0 * ldc + c;
                split2(acc[mt][nt][0] + b0, h0, l0);
                split2(acc[mt][nt][1] + b1, h1, l1);
                *reinterpret_cast<__nv_bfloat162*>(q0) = __halves2bfloat162(h0, h1);
                *reinterpret_cast<__nv_bfloat162*>(q0 + loOff) = __halves2bfloat162(l0, l1);
                u16* q1 = Cs + (long)r1 * ldc + c;
                split2(acc[mt][nt][2] + b0, h0, l0);
                split2(acc[mt][nt][3] + b1, h1, l1);
                *reinterpret_cast<__nv_bfloat162*>(q1) = __halves2bfloat162(h0, h1);
                *reinterpret_cast<__nv_bfloat162*>(q1 + loOff) = __halves2bfloat162(l0, l1);
            }
        }
    }
}

// Standalone GEMM kernel (S, PV)
template <int MODE, int BTRANS>
__global__ void __launch_bounds__(128, 2)
gemm_mma(const u16* __restrict__ A, const u16* __restrict__ B,
         const float* __restrict__ bias, float* __restrict__ Cf,
         u16* __restrict__ Cs,
         int K, int Kfull, int kPerZ,
         long sA, long sB, long sC, int ldc, int loOff, int ldb)
{
    gemm_body<MODE, BTRANS>(blockIdx.x, blockIdx.y, blockIdx.z,
                            A, B, bias, Cf, Cs, K, Kfull, kPerZ,
                            sA, sB, sC, ldc, loOff, ldb);
}

// fusedM: CTAs [0,4096) = ix split ; [4096, 4608) = M = W^T W split-K z=8
__global__ void __launch_bounds__(128, 2)
fusedM_kernel(const float* __restrict__ ix, u16* __restrict__ ixs,
              const u16* __restrict__ wts, float* __restrict__ mp)
{
    const int idx = blockIdx.x;
    if (idx < 4096) {
        split_body128(idx, ix, ixs);
    } else {
        const int i = idx - 4096;
        gemm_body<0, 0>(i & 7, (i >> 3) & 7, i >> 6,
                        wts, wts, nullptr, mp, nullptr,
                        128, 1024, 128,
                        0, 0, 1024L * 1024, 1024, 0, 0);
    }
}

// fusedT: CTAs [0,4096) = io split + v ; [4096, 5120) = T = ix @ M
__global__ void __launch_bounds__(128, 2)
fusedT_kernel(const float* __restrict__ io, const float* __restrict__ wtb,
              u16* __restrict__ ios, float* __restrict__ v,
              const u16* __restrict__ ixs, const u16* __restrict__ ms,
              u16* __restrict__ ts)
{
    const int idx = blockIdx.x;
    if (idx < 4096) {
        split_v_body128(idx, io, wtb, ios, v);
    } else {
        const int i = idx - 4096;
        gemm_body<1, 0>(i & 7, i >> 3, 0,
                        ixs, ms, nullptr, nullptr, ts,
                        1024, 1024, 0,
                        0, 0, 0, 2048, 1024, 0);
    }
}

// ======================= warp softmax(+v) + split ===========================
__global__ void __launch_bounds__(256)
softmax512_split_warp(const float* __restrict__ S, const float* __restrict__ v,
                      u16* __restrict__ P)
{
    const int gw   = (blockIdx.x * 256 + threadIdx.x) >> 5;
    const int lane = threadIdx.x & 31;
    const float* row = S + (long)gw * 512;
    const float* vb  = v + ((gw >> 9) << 9);
    u16* prow = P + (long)gw * 1024;

    float x[16];
    float mx = -1e30f;
#pragma unroll
    for (int i = 0; i < 4; i++) {
        const int c = i * 128 + lane * 4;
        const float4 a = *reinterpret_cast<const float4*>(row + c);
        const float4 w = *reinterpret_cast<const float4*>(vb + c);
        x[4 * i + 0] = a.x + w.x;
        x[4 * i + 1] = a.y + w.y;
        x[4 * i + 2] = a.z + w.z;
        x[4 * i + 3] = a.w + w.w;
        mx = fmaxf(mx, fmaxf(fmaxf(x[4 * i], x[4 * i + 1]),
                             fmaxf(x[4 * i + 2], x[4 * i + 3])));
    }
#pragma unroll
    for (int o = 16; o > 0; o >>= 1)
        mx = fmaxf(mx, __shfl_xor_sync(0xFFFFFFFFu, mx, o));

    float sum = 0.0f;
#pragma unroll
    for (int j = 0; j < 16; j++) {
        x[j] = __expf(x[j] - mx);
        sum += x[j];
    }
#pragma unroll
    for (int o = 16; o > 0; o >>= 1)
        sum += __shfl_xor_sync(0xFFFFFFFFu, sum, o);
    const float inv = 1.0f / sum;

#pragma unroll
    for (int i = 0; i < 4; i++) {
        const int c = i * 128 + lane * 4;
        float4 a;
        a.x = x[4 * i + 0] * inv;
        a.y = x[4 * i + 1] * inv;
        a.z = x[4 * i + 2] * inv;
        a.w = x[4 * i + 3] * inv;
        store_split4(prow + c, prow + 512 + c, a);
    }
}

// ======================= launch =============================================
extern "C" void kernel_launch(void* const* d_in, const int* in_sizes, int n_in,
                              void* d_out, int out_size)
{
    const float* ix = (const float*)d_in[0];   // [32, 512, 1024]
    const float* io = (const float*)d_in[1];   // [32, 512, 1024]
    const float* W  = (const float*)d_in[2];   // [1024, 1024]
    const float* bi = (const float*)d_in[3];   // [1024]
    float* out = (float*)d_out;                // [32, 512, 1024]

    u16 *wts, *ms, *ixs, *ios, *ts, *ps;
    float *mp, *sc, *wtb, *v;
    cudaGetSymbolAddress((void**)&wts,  g_wts);
    cudaGetSymbolAddress((void**)&mp,   g_mp);
    cudaGetSymbolAddress((void**)&ms,   g_ms);
    cudaGetSymbolAddress((void**)&ixs,  g_ixs);
    cudaGetSymbolAddress((void**)&ios,  g_ios);
    cudaGetSymbolAddress((void**)&ts,   g_ts);
    cudaGetSymbolAddress((void**)&sc,   g_sc);
    cudaGetSymbolAddress((void**)&ps,   g_ps);
    cudaGetSymbolAddress((void**)&wtb,  g_wtb);
    cudaGetSymbolAddress((void**)&v,    g_v);

    cudaFuncSetAttribute(gemm_mma<0, 0>, cudaFuncAttributeMaxDynamicSharedMemorySize, GEMM_SMEM);
    cudaFuncSetAttribute(gemm_mma<0, 1>, cudaFuncAttributeMaxDynamicSharedMemorySize, GEMM_SMEM);
    cudaFuncSetAttribute(fusedM_kernel,  cudaFuncAttributeMaxDynamicSharedMemorySize, GEMM_SMEM);
    cudaFuncSetAttribute(fusedT_kernel,  cudaFuncAttributeMaxDynamicSharedMemorySize, GEMM_SMEM);

    const int Bn = 32, L = 512, D = 1024;

    // zero atomic accumulators
    cudaMemsetAsync(wtb, 0, 1024 * sizeof(float));
    cudaMemsetAsync(v,   0, 16384 * sizeof(float));

    // 0) W^T split + wtb (one pass over W)
    {
        dim3 g(32, 32, 1);
        wsplit_wtb_kernel<<<g, 256>>>(W, bi, wts, wtb);
    }
    // 1) fused: ix split  ||  M = W^T W split-K z=8
    fusedM_kernel<<<4096 + 512, 128, GEMM_SMEM>>>(ix, ixs, wts, mp);
    // 2) reduce M partials + split -> ms   (D*D/1024 = 1024 CTAs — NOT 4096)
    reduce8_split_kernel<<<1024, 256>>>(mp, ms);
    // 3) fused: io split + v  ||  T = ix @ M
    fusedT_kernel<<<4096 + 1024, 128, GEMM_SMEM>>>(io, wtb, ios, v, ixs, ms, ts);
    // 4) S[b] = T[b] @ io[b]^T  (NT; fp32 out; v added in softmax)
    {
        dim3 g(L / 128, L / 128, Bn);
        gemm_mma<0, 0><<<g, 128, GEMM_SMEM>>>(ts, ios, nullptr, sc, nullptr,
                                              D, D, 0,
                                              (long)L * 2 * D, (long)L * 2 * D,
                                              (long)L * L, L, 0, 0);
    }
    // 5) warp softmax(S + v) + split probs
    softmax512_split_warp<<<(Bn * L) / 8, 256>>>(sc, v, ps);
    // 6) out[b] = P[b] @ io[b]  (NN via ldmatrix.trans; B = ios, lo at +1024)
    {
        dim3 g(D / 128, L / 128, Bn);
        gemm_mma<0, 1><<<g, 128, GEMM_SMEM>>>(ps, ios, nullptr, out, nullptr,
                                              L, L, 0,
                                              (long)L * 2 * L, (long)L * 2 * D,
                                              (long)L * D, D, 1024, 2 * D);
    }
}

// round 17
// speedup vs baseline: 1.0287x; 1.0287x over previous
#include <cuda_runtime.h>
#include <cuda_bf16.h>
#include <cstdint>

// ---------------------------------------------------------------------------
// Aligner, algebraic form:
//   softmax(ex@eo^T) == softmax(ix@(W^T W)@io^T + 1 v^T),  v = io @ (W^T b)
//   out = softmax(...) @ io
// Chain: M = W^T W (split-K z=8) ; T = ix M ; S = T io^T ;
//        P = softmax(S+v) ; out = P io (NN via ldmatrix.trans)
// R16: heterogeneous fusion with GEMM-FIRST CTA ordering (tail-fill): the
//      long tensor-bound GEMM CTAs occupy the slots first; the short
//      DRAM-bound split CTAs backfill the partial last GEMM wave.
// ---------------------------------------------------------------------------

typedef unsigned short u16;  // raw bf16 bits

// ======================= scratch (device globals) ===========================
__device__ u16   g_wts [1024L * 2048];      // W^T split
__device__ float g_mp  [8L * 1024 * 1024];  // M split-K partials (fp32, z=8)
__device__ u16   g_ms  [1024L * 2048];      // M = W^T W split
__device__ u16   g_ixs [16384L * 2048];     // ix split
__device__ u16   g_ios [16384L * 2048];     // io split
__device__ u16   g_ts  [16384L * 2048];     // T = ix M split
__device__ float g_sc  [32L * 512 * 512];   // scores fp32
__device__ u16   g_ps  [32L * 512 * 1024];  // softmax probs split
__device__ float g_wtb [1024];              // W^T b  (atomic accum)
__device__ float g_v   [16384];             // io @ (W^T b)  (atomic accum)

// ======================= PTX helpers ========================================
__device__ __forceinline__ uint32_t smem_u32(const void* p) {
    uint32_t a;
    asm("{ .reg .u64 t; cvta.to.shared.u64 t, %1; cvt.u32.u64 %0, t; }"
        : "=r"(a) : "l"(p));
    return a;
}

__device__ __forceinline__ void cp_async16(uint32_t saddr, const void* gaddr) {
    asm volatile("cp.async.cg.shared.global [%0], [%1], 16;"
                 :: "r"(saddr), "l"(gaddr) : "memory");
}
__device__ __forceinline__ void cp_commit() {
    asm volatile("cp.async.commit_group;" ::: "memory");
}
template <int N>
__device__ __forceinline__ void cp_wait() {
    asm volatile("cp.async.wait_group %0;" :: "n"(N) : "memory");
}

__device__ __forceinline__ void ldsm_x4(uint32_t* r, uint32_t addr) {
    asm volatile("ldmatrix.sync.aligned.m8n8.x4.shared.b16 {%0,%1,%2,%3}, [%4];"
                 : "=r"(r[0]), "=r"(r[1]), "=r"(r[2]), "=r"(r[3]) : "r"(addr));
}
__device__ __forceinline__ void ldsm_x4_trans(uint32_t* r, uint32_t addr) {
    asm volatile("ldmatrix.sync.aligned.m8n8.x4.trans.shared.b16 {%0,%1,%2,%3}, [%4];"
                 : "=r"(r[0]), "=r"(r[1]), "=r"(r[2]), "=r"(r[3]) : "r"(addr));
}

__device__ __forceinline__ void mma_bf16(float* c, const uint32_t* a,
                                         const uint32_t* b) {
    asm volatile(
        "mma.sync.aligned.m16n8k16.row.col.f32.bf16.bf16.f32 "
        "{%0,%1,%2,%3}, {%4,%5,%6,%7}, {%8,%9}, {%0,%1,%2,%3};"
        : "+f"(c[0]), "+f"(c[1]), "+f"(c[2]), "+f"(c[3])
        : "r"(a[0]), "r"(a[1]), "r"(a[2]), "r"(a[3]), "r"(b[0]), "r"(b[1]));
}

// ======================= split helpers ======================================
__device__ __forceinline__ void split2(float v, __nv_bfloat16& h, __nv_bfloat16& l) {
    h = __float2bfloat16(v);
    l = __float2bfloat16(v - __bfloat162float(h));
}

__device__ __forceinline__ void store_split4(u16* oh, u16* ol, float4 a) {
    __nv_bfloat16 h0, h1, h2, h3, l0, l1, l2, l3;
    split2(a.x, h0, l0); split2(a.y, h1, l1); split2(a.z, h2, l2); split2(a.w, h3, l3);
    *reinterpret_cast<__nv_bfloat162*>(oh)     = __halves2bfloat162(h0, h1);
    *reinterpret_cast<__nv_bfloat162*>(oh + 2) = __halves2bfloat162(h2, h3);
    *reinterpret_cast<__nv_bfloat162*>(ol)     = __halves2bfloat162(l0, l1);
    *reinterpret_cast<__nv_bfloat162*>(ol + 2) = __halves2bfloat162(l2, l3);
}

// 128-thread split body: CTA `cta` handles 8 half-rows (512 floats each) of a
// [R,1024] fp32 tensor -> [R, 2048] hi|lo split.
__device__ __forceinline__ void split_body128(int cta, const float* __restrict__ in,
                                              u16* __restrict__ out)
{
    const int t = threadIdx.x;
#pragma unroll
    for (int it = 0; it < 8; it++) {
        const int seg = cta * 8 + it;
        const long r  = seg >> 1;
        const int  cb = (seg & 1) * 512 + t * 4;
        const float4 a = *reinterpret_cast<const float4*>(in + r * 1024 + cb);
        store_split4(out + r * 2048 + cb, out + r * 2048 + 1024 + cb, a);
    }
}

// same + v[r] += sum(row * wtb) partials (warp covers 128 contiguous cols)
__device__ __forceinline__ void split_v_body128(int cta, const float* __restrict__ in,
                                                const float* __restrict__ wtb,
                                                u16* __restrict__ out,
                                                float* __restrict__ v)
{
    const int t = threadIdx.x;
#pragma unroll
    for (int it = 0; it < 8; it++) {
        const int seg = cta * 8 + it;
        const long r  = seg >> 1;
        const int  cb = (seg & 1) * 512 + t * 4;
        const float4 a = *reinterpret_cast<const float4*>(in + r * 1024 + cb);
        const float4 w = *reinterpret_cast<const float4*>(wtb + cb);
        store_split4(out + r * 2048 + cb, out + r * 2048 + 1024 + cb, a);
        float s = a.x * w.x + a.y * w.y + a.z * w.z + a.w * w.w;
#pragma unroll
        for (int o = 16; o > 0; o >>= 1)
            s += __shfl_xor_sync(0xFFFFFFFFu, s, o);
        if ((t & 31) == 0) atomicAdd(&v[r], s);
    }
}

// W^T split + wtb partials in one pass over W.  grid (32, 32), 256 thr.
__global__ void __launch_bounds__(256)
wsplit_wtb_kernel(const float* __restrict__ W, const float* __restrict__ b,
                  u16* __restrict__ out, float* __restrict__ wtb)
{
    __shared__ float t[32][33];
    __shared__ float red[8][32];
    const int d0 = blockIdx.x * 32;
    const int m0 = blockIdx.y * 32;   // e range
    const int tx = threadIdx.x & 31;
    const int ty = threadIdx.x >> 5;
    float part = 0.0f;
#pragma unroll
    for (int i = 0; i < 4; i++) {
        const int e = m0 + ty + 8 * i;
        const float val = W[(long)e * 1024 + d0 + tx];
        t[ty + 8 * i][tx] = val;
        part += val * b[e];
    }
    red[ty][tx] = part;
    __syncthreads();
    if (ty == 0) {
        float s = red[0][tx];
#pragma unroll
        for (int i = 1; i < 8; i++) s += red[i][tx];
        atomicAdd(&wtb[d0 + tx], s);
    }
#pragma unroll
    for (int i = 0; i < 4; i++) {
        const int d = d0 + ty + 8 * i;
        const int m = m0 + tx;
        __nv_bfloat16 h, l;
        split2(t[tx][ty + 8 * i], h, l);
        *reinterpret_cast<__nv_bfloat16*>(&out[(long)d * 2048 + m])        = h;
        *reinterpret_cast<__nv_bfloat16*>(&out[(long)d * 2048 + 1024 + m]) = l;
    }
}

// sum 8 split-K partials of M and split to bf16 hi/lo.  grid = 1024 CTAs.
__global__ void __launch_bounds__(256)
reduce8_split_kernel(const float* __restrict__ p, u16* __restrict__ out)
{
    const long e = ((long)blockIdx.x * 256 + threadIdx.x) * 4;
    const long r = e >> 10;
    const int  c = (int)(e & 1023);
    float4 a = *reinterpret_cast<const float4*>(p + e);
#pragma unroll
    for (int s = 1; s < 8; s++) {
        const float4 b = *reinterpret_cast<const float4*>(p + (long)s * 1048576 + e);
        a.x += b.x; a.y += b.y; a.z += b.z; a.w += b.w;
    }
    store_split4(out + r * 2048 + c, out + r * 2048 + 1024 + c, a);
}

// ======================= mma.sync GEMM engine (device body) =================
// NT (BTRANS=0): C = A[M,2Kfull] (*) B[N,2Kfull], B row-major [N,K].
// NN (BTRANS=1): C = A[M,2Kfull] (*) B[K,ldb] row-major; hi at col0, lo at
//                col0+loOff; fragments via ldmatrix.trans.
// 3 bf16 phases, fp32 accumulate. CTA 128x128, 4 warps (2Mx2N of 64x64),
// 2-stage cp.async, 2 CTAs/SM.
#define LDS_STRIDE 40
#define BSTRIDE 136
#define TILE_BYTES (128 * LDS_STRIDE * 2)
#define STAGE_BYTES (4 * TILE_BYTES)
#define GEMM_SMEM (2 * STAGE_BYTES)

template <int MODE, int BTRANS>
__device__ __forceinline__ void
gemm_body(int gbx, int gby, int gbz,
          const u16* __restrict__ A, const u16* __restrict__ B,
          const float* __restrict__ bias, float* __restrict__ Cf,
          u16* __restrict__ Cs,
          int K, int Kfull, int kPerZ,
          long sA, long sB, long sC, int ldc, int loOff, int ldb)
{
    extern __shared__ char dynsmem[];

    const int tid  = threadIdx.x;
    const int wid  = tid >> 5;
    const int lane = tid & 31;

    const long bz = gbz;
    A += bz * sA;
    B += bz * sB;
    const int kbase = (int)bz * kPerZ;
    const int row0 = gby * 128;
    const int col0 = gbx * 128;
    const long lda = 2L * Kfull;

    const int nkc = K / 32;

    const uint32_t sbase = smem_u32(dynsmem);

    const int cr0 = tid >> 2;
    const int cc  = tid & 3;

    const int warp_m = wid & 1;
    const int warp_n = wid >> 1;

    float acc[4][8][4];
#pragma unroll
    for (int mt = 0; mt < 4; mt++)
#pragma unroll
        for (int nt = 0; nt < 8; nt++)
#pragma unroll
            for (int i = 0; i < 4; i++) acc[mt][nt][i] = 0.0f;

    const int a_row = warp_m * 64 + (lane & 15);
    const int a_colb = (lane >> 4) << 3;
    const int b_row = warp_n * 64 + (lane & 7) + ((lane >> 4) << 3);
    const int b_colb = ((lane >> 3) & 1) << 3;
    const int bk = (lane & 7) + (((lane >> 3) & 1) << 3);
    const int bn = warp_n * 64 + ((lane >> 4) << 3);

    auto stage_copy = [&](int s, int kc) {
        const uint32_t sb0 = sbase + (uint32_t)s * STAGE_BYTES;
        const int hoff = kbase + kc * 32;
        const int loff = Kfull + kbase + kc * 32;
#pragma unroll
        for (int j = 0; j < 4; j++) {
            const int r = cr0 + 32 * j;
            const uint32_t so = (uint32_t)r * (LDS_STRIDE * 2) + (uint32_t)cc * 16u;
            const u16* arow = A + (long)(row0 + r) * lda + cc * 8;
            cp_async16(sb0 + 0 * TILE_BYTES + so, arow + hoff);
            cp_async16(sb0 + 1 * TILE_BYTES + so, arow + loff);
        }
        if (!BTRANS) {
#pragma unroll
            for (int j = 0; j < 4; j++) {
                const int r = cr0 + 32 * j;
                const uint32_t so = (uint32_t)r * (LDS_STRIDE * 2) + (uint32_t)cc * 16u;
                const u16* brow = B + (long)(col0 + r) * lda + cc * 8;
                cp_async16(sb0 + 2 * TILE_BYTES + so, brow + hoff);
                cp_async16(sb0 + 3 * TILE_BYTES + so, brow + loff);
            }
        } else {
#pragma unroll
            for (int j = 0; j < 4; j++) {
                const int vv = tid + 128 * j;
                const int krow = vv >> 4;
                const int vc   = vv & 15;
                const uint32_t so = (uint32_t)krow * (BSTRIDE * 2) + (uint32_t)vc * 16u;
                const u16* brow = B + (long)(kbase + kc * 32 + krow) * ldb
                                    + col0 + vc * 8;
                cp_async16(sb0 + 2 * TILE_BYTES + so, brow);
                cp_async16(sb0 + 3 * TILE_BYTES + so, brow + loOff);
            }
        }
        cp_commit();
    };

    stage_copy(0, 0);

    for (int kc = 0; kc < nkc; kc++) {
        cp_wait<0>();
        __syncthreads();

        const uint32_t st = sbase + (uint32_t)(kc & 1) * STAGE_BYTES;
        const uint32_t stAl = st + 1 * TILE_BYTES;
        const uint32_t stBh = st + 2 * TILE_BYTES;
        const uint32_t stBl = st + 3 * TILE_BYTES;

        uint32_t ah[4][4], al[4][4], bh[8][2], bl[8][2];
        {
            const uint32_t a_off =
                (uint32_t)a_row * (LDS_STRIDE * 2) + (uint32_t)a_colb * 2;
#pragma unroll
            for (int mt = 0; mt < 4; mt++) {
                const uint32_t ao = a_off + (uint32_t)(mt * 16) * (LDS_STRIDE * 2);
                ldsm_x4(ah[mt], st + ao);
                ldsm_x4(al[mt], stAl + ao);
            }
#pragma unroll
            for (int nt2 = 0; nt2 < 4; nt2++) {
                uint32_t r4[4], s4[4];
                if (!BTRANS) {
                    const uint32_t bo =
                        (uint32_t)(b_row + nt2 * 16) * (LDS_STRIDE * 2) +
                        (uint32_t)b_colb * 2;
                    ldsm_x4(r4, stBh + bo);
                    ldsm_x4(s4, stBl + bo);
                } else {
                    const uint32_t bo =
                        (uint32_t)bk * (BSTRIDE * 2) +
                        (uint32_t)(bn + nt2 * 16) * 2;
                    ldsm_x4_trans(r4, stBh + bo);
                    ldsm_x4_trans(s4, stBl + bo);
                }
                bh[2 * nt2][0] = r4[0]; bh[2 * nt2][1] = r4[1];
                bh[2 * nt2 + 1][0] = r4[2]; bh[2 * nt2 + 1][1] = r4[3];
                bl[2 * nt2][0] = s4[0]; bl[2 * nt2][1] = s4[1];
                bl[2 * nt2 + 1][0] = s4[2]; bl[2 * nt2 + 1][1] = s4[3];
            }
        }

        if (kc + 1 < nkc) stage_copy((kc + 1) & 1, kc + 1);

#pragma unroll
        for (int mt = 0; mt < 4; mt++)
#pragma unroll
            for (int nt = 0; nt < 8; nt++)
                mma_bf16(acc[mt][nt], ah[mt], bh[nt]);
#pragma unroll
        for (int mt = 0; mt < 4; mt++)
#pragma unroll
            for (int nt = 0; nt < 8; nt++)
                mma_bf16(acc[mt][nt], ah[mt], bl[nt]);
#pragma unroll
        for (int mt = 0; mt < 4; mt++)
#pragma unroll
            for (int nt = 0; nt < 8; nt++)
                mma_bf16(acc[mt][nt], al[mt], bh[nt]);

        {
            const uint32_t a_off =
                (uint32_t)a_row * (LDS_STRIDE * 2) + (uint32_t)(16 + a_colb) * 2;
#pragma unroll
            for (int mt = 0; mt < 4; mt++) {
                const uint32_t ao = a_off + (uint32_t)(mt * 16) * (LDS_STRIDE * 2);
                ldsm_x4(ah[mt], st + ao);
                ldsm_x4(al[mt], stAl + ao);
            }
#pragma unroll
            for (int nt2 = 0; nt2 < 4; nt2++) {
                uint32_t r4[4], s4[4];
                if (!BTRANS) {
                    const uint32_t bo =
                        (uint32_t)(b_row + nt2 * 16) * (LDS_STRIDE * 2) +
                        (uint32_t)(16 + b_colb) * 2;
                    ldsm_x4(r4, stBh + bo);
                    ldsm_x4(s4, stBl + bo);
                } else {
                    const uint32_t bo =
                        (uint32_t)(16 + bk) * (BSTRIDE * 2) +
                        (uint32_t)(bn + nt2 * 16) * 2;
                    ldsm_x4_trans(r4, stBh + bo);
                    ldsm_x4_trans(s4, stBl + bo);
                }
                bh[2 * nt2][0] = r4[0]; bh[2 * nt2][1] = r4[1];
                bh[2 * nt2 + 1][0] = r4[2]; bh[2 * nt2 + 1][1] = r4[3];
                bl[2 * nt2][0] = s4[0]; bl[2 * nt2][1] = s4[1];
                bl[2 * nt2 + 1][0] = s4[2]; bl[2 * nt2 + 1][1] = s4[3];
            }
        }
#pragma unroll
        for (int mt = 0; mt < 4; mt++)
#pragma unroll
            for (int nt = 0; nt < 8; nt++)
                mma_bf16(acc[mt][nt], ah[mt], bh[nt]);
#pragma unroll
        for (int mt = 0; mt < 4; mt++)
#pragma unroll
            for (int nt = 0; nt < 8; nt++)
                mma_bf16(acc[mt][nt], ah[mt], bl[nt]);
#pragma unroll
        for (int mt = 0; mt < 4; mt++)
#pragma unroll
            for (int nt = 0; nt < 8; nt++)
                mma_bf16(acc[mt][nt], al[mt], bh[nt]);
    }

    // ---- epilogue ----
    const int er0 = row0 + warp_m * 64 + (lane >> 2);
    const int ec0 = col0 + warp_n * 64 + (lane & 3) * 2;
#pragma unroll
    for (int mt = 0; mt < 4; mt++) {
#pragma unroll
        for (int nt = 0; nt < 8; nt++) {
            const int r0 = er0 + mt * 16;
            const int r1 = r0 + 8;
            const int c  = ec0 + nt * 8;
            if (MODE == 0) {
                float2 v0, v1;
                v0.x = acc[mt][nt][0]; v0.y = acc[mt][nt][1];
                v1.x = acc[mt][nt][2]; v1.y = acc[mt][nt][3];
                *reinterpret_cast<float2*>(Cf + bz * sC + (long)r0 * ldc + c) = v0;
                *reinterpret_cast<float2*>(Cf + bz * sC + (long)r1 * ldc + c) = v1;
            } else {
                const float b0 = bias ? bias[c] : 0.0f;
                const float b1 = bias ? bias[c + 1] : 0.0f;
                __nv_bfloat16 h0, h1, l0, l1;
                u16* q0 = Cs + (long)r0 * ldc + c;
                split2(acc[mt][nt][0] + b0, h0, l0);
                split2(acc[mt][nt][1] + b1, h1, l1);
                *reinterpret_cast<__nv_bfloat162*>(q0) = __halves2bfloat162(h0, h1);
                *reinterpret_cast<__nv_bfloat162*>(q0 + loOff) = __halves2bfloat162(l0, l1);
                u16* q1 = Cs + (long)r1 * ldc + c;
                split2(acc[mt][nt][2] + b0, h0, l0);
                split2(acc[mt][nt][3] + b1, h1, l1);
                *reinterpret_cast<__nv_bfloat162*>(q1) = __halves2bfloat162(h0, h1);
                *reinterpret_cast<__nv_bfloat162*>(q1 + loOff) = __halves2bfloat162(l0, l1);
            }
        }
    }
}

// Standalone GEMM kernel (S, PV)
template <int MODE, int BTRANS>
__global__ void __launch_bounds__(128, 2)
gemm_mma(const u16* __restrict__ A, const u16* __restrict__ B,
         const float* __restrict__ bias, float* __restrict__ Cf,
         u16* __restrict__ Cs,
         int K, int Kfull, int kPerZ,
         long sA, long sB, long sC, int ldc, int loOff, int ldb)
{
    gemm_body<MODE, BTRANS>(blockIdx.x, blockIdx.y, blockIdx.z,
                            A, B, bias, Cf, Cs, K, Kfull, kPerZ,
                            sA, sB, sC, ldc, loOff, ldb);
}

// fusedM (GEMM FIRST): CTAs [0,512) = M split-K z=8 ; [512, 4608) = ix split
__global__ void __launch_bounds__(128, 2)
fusedM_kernel(const float* __restrict__ ix, u16* __restrict__ ixs,
              const u16* __restrict__ wts, float* __restrict__ mp)
{
    const int idx = blockIdx.x;
    if (idx < 512) {
        gemm_body<0, 0>(idx & 7, (idx >> 3) & 7, idx >> 6,
                        wts, wts, nullptr, mp, nullptr,
                        128, 1024, 128,
                        0, 0, 1024L * 1024, 1024, 0, 0);
    } else {
        split_body128(idx - 512, ix, ixs);
    }
}

// fusedT (GEMM FIRST): CTAs [0,1024) = T = ix @ M ; [1024, 5120) = io split + v
__global__ void __launch_bounds__(128, 2)
fusedT_kernel(const float* __restrict__ io, const float* __restrict__ wtb,
              u16* __restrict__ ios, float* __restrict__ v,
              const u16* __restrict__ ixs, const u16* __restrict__ ms,
              u16* __restrict__ ts)
{
    const int idx = blockIdx.x;
    if (idx < 1024) {
        gemm_body<1, 0>(idx & 7, idx >> 3, 0,
                        ixs, ms, nullptr, nullptr, ts,
                        1024, 1024, 0,
                        0, 0, 0, 2048, 1024, 0);
    } else {
        split_v_body128(idx - 1024, io, wtb, ios, v);
    }
}

// ======================= warp softmax(+v) + split ===========================
__global__ void __launch_bounds__(256)
softmax512_split_warp(const float* __restrict__ S, const float* __restrict__ v,
                      u16* __restrict__ P)
{
    const int gw   = (blockIdx.x * 256 + threadIdx.x) >> 5;
    const int lane = threadIdx.x & 31;
    const float* row = S + (long)gw * 512;
    const float* vb  = v + ((gw >> 9) << 9);
    u16* prow = P + (long)gw * 1024;

    float x[16];
    float mx = -1e30f;
#pragma unroll
    for (int i = 0; i < 4; i++) {
        const int c = i * 128 + lane * 4;
        const float4 a = *reinterpret_cast<const float4*>(row + c);
        const float4 w = *reinterpret_cast<const float4*>(vb + c);
        x[4 * i + 0] = a.x + w.x;
        x[4 * i + 1] = a.y + w.y;
        x[4 * i + 2] = a.z + w.z;
        x[4 * i + 3] = a.w + w.w;
        mx = fmaxf(mx, fmaxf(fmaxf(x[4 * i], x[4 * i + 1]),
                             fmaxf(x[4 * i + 2], x[4 * i + 3])));
    }
#pragma unroll
    for (int o = 16; o > 0; o >>= 1)
        mx = fmaxf(mx, __shfl_xor_sync(0xFFFFFFFFu, mx, o));

    float sum = 0.0f;
#pragma unroll
    for (int j = 0; j < 16; j++) {
        x[j] = __expf(x[j] - mx);
        sum += x[j];
    }
#pragma unroll
    for (int o = 16; o > 0; o >>= 1)
        sum += __shfl_xor_sync(0xFFFFFFFFu, sum, o);
    const float inv = 1.0f / sum;

#pragma unroll
    for (int i = 0; i < 4; i++) {
        const int c = i * 128 + lane * 4;
        float4 a;
        a.x = x[4 * i + 0] * inv;
        a.y = x[4 * i + 1] * inv;
        a.z = x[4 * i + 2] * inv;
        a.w = x[4 * i + 3] * inv;
        store_split4(prow + c, prow + 512 + c, a);
    }
}

// ======================= launch =============================================
extern "C" void kernel_launch(void* const* d_in, const int* in_sizes, int n_in,
                              void* d_out, int out_size)
{
    const float* ix = (const float*)d_in[0];   // [32, 512, 1024]
    const float* io = (const float*)d_in[1];   // [32, 512, 1024]
    const float* W  = (const float*)d_in[2];   // [1024, 1024]
    const float* bi = (const float*)d_in[3];   // [1024]
    float* out = (float*)d_out;                // [32, 512, 1024]

    u16 *wts, *ms, *ixs, *ios, *ts, *ps;
    float *mp, *sc, *wtb, *v;
    cudaGetSymbolAddress((void**)&wts,  g_wts);
    cudaGetSymbolAddress((void**)&mp,   g_mp);
    cudaGetSymbolAddress((void**)&ms,   g_ms);
    cudaGetSymbolAddress((void**)&ixs,  g_ixs);
    cudaGetSymbolAddress((void**)&ios,  g_ios);
    cudaGetSymbolAddress((void**)&ts,   g_ts);
    cudaGetSymbolAddress((void**)&sc,   g_sc);
    cudaGetSymbolAddress((void**)&ps,   g_ps);
    cudaGetSymbolAddress((void**)&wtb,  g_wtb);
    cudaGetSymbolAddress((void**)&v,    g_v);

    cudaFuncSetAttribute(gemm_mma<0, 0>, cudaFuncAttributeMaxDynamicSharedMemorySize, GEMM_SMEM);
    cudaFuncSetAttribute(gemm_mma<0, 1>, cudaFuncAttributeMaxDynamicSharedMemorySize, GEMM_SMEM);
    cudaFuncSetAttribute(fusedM_kernel,  cudaFuncAttributeMaxDynamicSharedMemorySize, GEMM_SMEM);
    cudaFuncSetAttribute(fusedT_kernel,  cudaFuncAttributeMaxDynamicSharedMemorySize, GEMM_SMEM);

    const int Bn = 32, L = 512, D = 1024;

    // zero atomic accumulators
    cudaMemsetAsync(wtb, 0, 1024 * sizeof(float));
    cudaMemsetAsync(v,   0, 16384 * sizeof(float));

    // 0) W^T split + wtb (one pass over W)
    {
        dim3 g(32, 32, 1);
        wsplit_wtb_kernel<<<g, 256>>>(W, bi, wts, wtb);
    }
    // 1) fused: M = W^T W split-K z=8 (first)  ||  ix split (tail-fill)
    fusedM_kernel<<<512 + 4096, 128, GEMM_SMEM>>>(ix, ixs, wts, mp);
    // 2) reduce M partials + split -> ms   (1024 CTAs)
    reduce8_split_kernel<<<1024, 256>>>(mp, ms);
    // 3) fused: T = ix @ M (first)  ||  io split + v (tail-fill)
    fusedT_kernel<<<1024 + 4096, 128, GEMM_SMEM>>>(io, wtb, ios, v, ixs, ms, ts);
    // 4) S[b] = T[b] @ io[b]^T  (NT; fp32 out; v added in softmax)
    {
        dim3 g(L / 128, L / 128, Bn);
        gemm_mma<0, 0><<<g, 128, GEMM_SMEM>>>(ts, ios, nullptr, sc, nullptr,
                                              D, D, 0,
                                              (long)L * 2 * D, (long)L * 2 * D,
                                              (long)L * L, L, 0, 0);
    }
    // 5) warp softmax(S + v) + split probs
    softmax512_split_warp<<<(Bn * L) / 8, 256>>>(sc, v, ps);
    // 6) out[b] = P[b] @ io[b]  (NN via ldmatrix.trans; B = ios, lo at +1024)
    {
        dim3 g(D / 128, L / 128, Bn);
        gemm_mma<0, 1><<<g, 128, GEMM_SMEM>>>(ps, ios, nullptr, out, nullptr,
                                              L, L, 0,
                                              (long)L * 2 * L, (long)L * 2 * D,
                                              (long)L * D, D, 1024, 2 * D);
    }
}